// round 1
// baseline (speedup 1.0000x reference)
#include <cuda_runtime.h>
#include <math.h>

#define NPTS 200000
#define CCH  128
#define EPSV 1e-5f

// ---------------- scratch (device globals; no allocations anywhere) ----------
__device__ float g_x[NPTS * CCH];     // BUF0: pooled voxel feats / residual / block output
__device__ float g_y[NPTS * CCH];     // BUF1: conv output
__device__ float g_a[NPTS * CCH];     // BUF2: post-BN activation
__device__ float g_cnt[NPTS];         // per-voxel point count
__device__ float g_stats[256];        // BN sums: [0..127]=sum, [128..255]=sumsq

// ---------------- zero kernels ----------------
__global__ void zero_pool_kernel(float* x, float* cnt, int M) {
    int total = M * CCH;
    for (int i = blockIdx.x * blockDim.x + threadIdx.x; i < total; i += gridDim.x * blockDim.x)
        x[i] = 0.f;
    for (int i = blockIdx.x * blockDim.x + threadIdx.x; i < M; i += gridDim.x * blockDim.x)
        cnt[i] = 0.f;
}

__global__ void zero_stats_kernel(float* stats) {
    stats[threadIdx.x] = 0.f;
}

// ---------------- encoder: Linear(14->128) + LayerNorm + ReLU + segment-sum --
__global__ __launch_bounds__(128)
void encode_pool_kernel(const float* __restrict__ gp,
                        const float* __restrict__ w_enc,
                        const float* __restrict__ b_enc,
                        const float* __restrict__ ln_g,
                        const float* __restrict__ ln_b,
                        const int*   __restrict__ inv_idx,
                        float* __restrict__ xsum,
                        float* __restrict__ cnt,
                        int Np) {
    const int c = threadIdx.x;           // channel 0..127
    __shared__ float sg[14];
    __shared__ float red[8];

    const float be = b_enc[c];
    const float lg = ln_g[c];
    const float lb = ln_b[c];

    for (int i = blockIdx.x; i < Np; i += gridDim.x) {
        if (c < 14) sg[c] = gp[i * 14 + c];
        __syncthreads();
        float f = be;
#pragma unroll
        for (int k = 0; k < 14; ++k) f += sg[k] * w_enc[k * CCH + c];
        // block reduce sum & sumsq over 128 channels
        float s = f, s2 = f * f;
#pragma unroll
        for (int off = 16; off > 0; off >>= 1) {
            s  += __shfl_xor_sync(0xffffffffu, s,  off);
            s2 += __shfl_xor_sync(0xffffffffu, s2, off);
        }
        int w = c >> 5;
        if ((c & 31) == 0) { red[w] = s; red[4 + w] = s2; }
        __syncthreads();
        float mu = (red[0] + red[1] + red[2] + red[3]) * (1.f / 128.f);
        float ms = (red[4] + red[5] + red[6] + red[7]) * (1.f / 128.f);
        float inv = rsqrtf(ms - mu * mu + EPSV);
        float v = fmaxf((f - mu) * inv * lg + lb, 0.f);
        int vox = inv_idx[i];
        atomicAdd(&xsum[vox * CCH + c], v);
        if (c == 0) atomicAdd(&cnt[vox], 1.f);
        __syncthreads();   // protect sg/red before next point
    }
}

// ---------------- divide pooled sums by counts --------------------------------
__global__ void pool_div_kernel(float* __restrict__ x, const float* __restrict__ cnt, int M) {
    int total = M * CCH;
    for (int i = blockIdx.x * blockDim.x + threadIdx.x; i < total; i += gridDim.x * blockDim.x)
        x[i] = x[i] / cnt[i >> 7];
}

// ---------------- submanifold 3x3x3 conv: y = sum_o gather(x, o)*mask @ W[o] --
// 32 voxels x 128 channels per 256-thread block; 4x4 microtile per thread.
__global__ __launch_bounds__(256)
void subm_conv_kernel(const float* __restrict__ xin,
                      const float* __restrict__ W,      // 27 x 128 x 128
                      const int*   __restrict__ nbr_idx,
                      const float* __restrict__ nbr_mask,
                      float* __restrict__ y,
                      int M) {
    __shared__ float As[32][33];      // [row t][k] (pitch 33 avoids store conflicts)
    __shared__ float Bs[32 * 128];    // [k][c] chunk of W[o]
    __shared__ int   nidxs[32];
    __shared__ float nmsks[32];
    __shared__ int   s_skip;

    const int tid  = threadIdx.x;
    const int lane = tid & 31;        // column group: cols lane*4..+3
    const int warp = tid >> 5;        // row group:    rows warp*4..+3
    const int v0   = blockIdx.x * 32;

    const int tA = tid >> 3;          // 0..31: A-load row
    const int kA = (tid & 7) * 4;     // 0,4,...,28: A-load k base

    float4 acc0 = make_float4(0, 0, 0, 0);
    float4 acc1 = make_float4(0, 0, 0, 0);
    float4 acc2 = make_float4(0, 0, 0, 0);
    float4 acc3 = make_float4(0, 0, 0, 0);

    for (int o = 0; o < 27; ++o) {
        if (tid < 32) {
            int v = v0 + tid;
            int id = 0; float mk = 0.f;
            if (v < M) { id = nbr_idx[v * 27 + o]; mk = nbr_mask[v * 27 + o]; }
            nidxs[tid] = id; nmsks[tid] = mk;
            unsigned bal = __ballot_sync(0xffffffffu, mk != 0.f);
            if (tid == 0) s_skip = (bal == 0u);
        }
        __syncthreads();
        if (s_skip) { __syncthreads(); continue; }

        const float* Wo = W + o * (CCH * CCH);
#pragma unroll
        for (int kk = 0; kk < 4; ++kk) {
            // stage gathered+masked A chunk
            float mk = nmsks[tA];
            float4 a = make_float4(0, 0, 0, 0);
            if (mk != 0.f) {
                a = *(const float4*)(xin + (size_t)nidxs[tA] * CCH + kk * 32 + kA);
                a.x *= mk; a.y *= mk; a.z *= mk; a.w *= mk;
            }
            As[tA][kA + 0] = a.x; As[tA][kA + 1] = a.y;
            As[tA][kA + 2] = a.z; As[tA][kA + 3] = a.w;
            // stage W chunk (contiguous 4096 floats)
            const float4* Bg  = (const float4*)(Wo + kk * 32 * CCH);
            float4*       Bsv = (float4*)Bs;
#pragma unroll
            for (int q = 0; q < 4; ++q) Bsv[tid + q * 256] = Bg[tid + q * 256];
            __syncthreads();

#pragma unroll 8
            for (int k = 0; k < 32; ++k) {
                float4 b = *(const float4*)&Bs[k * CCH + lane * 4];
                float a0 = As[warp * 4 + 0][k];
                float a1 = As[warp * 4 + 1][k];
                float a2 = As[warp * 4 + 2][k];
                float a3 = As[warp * 4 + 3][k];
                acc0.x += a0 * b.x; acc0.y += a0 * b.y; acc0.z += a0 * b.z; acc0.w += a0 * b.w;
                acc1.x += a1 * b.x; acc1.y += a1 * b.y; acc1.z += a1 * b.z; acc1.w += a1 * b.w;
                acc2.x += a2 * b.x; acc2.y += a2 * b.y; acc2.z += a2 * b.z; acc2.w += a2 * b.w;
                acc3.x += a3 * b.x; acc3.y += a3 * b.y; acc3.z += a3 * b.z; acc3.w += a3 * b.w;
            }
            __syncthreads();
        }
    }

    int vr = v0 + warp * 4;
    if (vr + 0 < M) *(float4*)&y[(size_t)(vr + 0) * CCH + lane * 4] = acc0;
    if (vr + 1 < M) *(float4*)&y[(size_t)(vr + 1) * CCH + lane * 4] = acc1;
    if (vr + 2 < M) *(float4*)&y[(size_t)(vr + 2) * CCH + lane * 4] = acc2;
    if (vr + 3 < M) *(float4*)&y[(size_t)(vr + 3) * CCH + lane * 4] = acc3;
}

// ---------------- BN stats: per-channel sum & sumsq over M rows ---------------
__global__ __launch_bounds__(128)
void bn_stats_kernel(const float* __restrict__ y, float* __restrict__ stats, int M) {
    const int c = threadIdx.x;
    float s1 = 0.f, s2 = 0.f;
    for (int r = blockIdx.x; r < M; r += gridDim.x) {
        float v = y[(size_t)r * CCH + c];
        s1 += v; s2 += v * v;
    }
    atomicAdd(&stats[c], s1);
    atomicAdd(&stats[128 + c], s2);
}

// ---------------- BN apply (+optional residual) + ReLU ------------------------
__global__ void bn_apply_kernel(const float* __restrict__ y,
                                const float* __restrict__ g,
                                const float* __restrict__ b,
                                const float* __restrict__ stats,
                                const float* __restrict__ residual,   // may be null
                                float* __restrict__ out,
                                int M) {
    int total = M * CCH;
    float invM = 1.f / (float)M;
    for (int i = blockIdx.x * blockDim.x + threadIdx.x; i < total; i += gridDim.x * blockDim.x) {
        int c = i & 127;
        float m   = stats[c] * invM;
        float var = stats[128 + c] * invM - m * m;
        float inv = rsqrtf(var + EPSV);
        float v = (y[i] - m) * inv * g[c] + b[c];
        if (residual) v += residual[i];
        out[i] = fmaxf(v, 0.f);
    }
}

// ---------------- head: gather + MLP(128->64->14) + residual add --------------
__global__ __launch_bounds__(128)
void head_kernel(const float* __restrict__ x,
                 const float* __restrict__ gp,
                 const int*   __restrict__ inv_idx,
                 const float* __restrict__ w1, const float* __restrict__ b1,
                 const float* __restrict__ w2, const float* __restrict__ b2,
                 float* __restrict__ out, int Np) {
    __shared__ float w1s[CCH * 64];
    __shared__ float w2s[64 * 14];
    __shared__ float b1s[64];
    __shared__ float b2s[14];
    __shared__ float pfs[2][CCH];
    __shared__ float hs[2][64];

    const int tid = threadIdx.x;
    for (int i = tid; i < CCH * 64; i += 128) w1s[i] = w1[i];
    for (int i = tid; i < 64 * 14; i += 128) w2s[i] = w2[i];
    if (tid < 64) b1s[tid] = b1[tid];
    if (tid < 14) b2s[tid] = b2[tid];
    __syncthreads();

    const int h = tid >> 6;   // which of the 2 points this half-block handles
    const int j = tid & 63;

    for (int ip = blockIdx.x * 2; ip < Np; ip += gridDim.x * 2) {
        int i = ip + h;
        bool ok = (i < Np);
        if (ok) {
            int v = inv_idx[i];
            pfs[h][j]      = x[(size_t)v * CCH + j];
            pfs[h][j + 64] = x[(size_t)v * CCH + j + 64];
        }
        __syncthreads();
        if (ok) {
            float acc = b1s[j];
#pragma unroll 8
            for (int k = 0; k < CCH; ++k) acc += pfs[h][k] * w1s[k * 64 + j];
            hs[h][j] = fmaxf(acc, 0.f);
        }
        __syncthreads();
        if (ok && j < 14) {
            float d = b2s[j];
#pragma unroll
            for (int k = 0; k < 64; ++k) d += hs[h][k] * w2s[k * 14 + j];
            out[(size_t)i * 14 + j] = gp[(size_t)i * 14 + j] + d;
        }
        __syncthreads();
    }
}

// ---------------- launch -------------------------------------------------------
extern "C" void kernel_launch(void* const* d_in, const int* in_sizes, int n_in,
                              void* d_out, int out_size) {
    const float* gp       = (const float*)d_in[0];
    const float* w_enc    = (const float*)d_in[1];
    const float* b_enc    = (const float*)d_in[2];
    const float* ln_g     = (const float*)d_in[3];
    const float* ln_b     = (const float*)d_in[4];
    const float* conv_w   = (const float*)d_in[5];
    const float* bn_g     = (const float*)d_in[6];
    const float* bn_b     = (const float*)d_in[7];
    const float* w1       = (const float*)d_in[8];
    const float* b1       = (const float*)d_in[9];
    const float* w2       = (const float*)d_in[10];
    const float* b2       = (const float*)d_in[11];
    const float* nbr_mask = (const float*)d_in[12];
    const int*   inv_idx  = (const int*)d_in[13];
    const int*   nbr_idx  = (const int*)d_in[14];
    float* out = (float*)d_out;

    const int Np = in_sizes[0] / 14;
    const int M  = in_sizes[12] / 27;

    float *px, *py, *pa, *pcnt, *pstats;
    cudaGetSymbolAddress((void**)&px,     g_x);
    cudaGetSymbolAddress((void**)&py,     g_y);
    cudaGetSymbolAddress((void**)&pa,     g_a);
    cudaGetSymbolAddress((void**)&pcnt,   g_cnt);
    cudaGetSymbolAddress((void**)&pstats, g_stats);

    zero_pool_kernel<<<1024, 256>>>(px, pcnt, M);
    encode_pool_kernel<<<4096, 128>>>(gp, w_enc, b_enc, ln_g, ln_b, inv_idx, px, pcnt, Np);
    pool_div_kernel<<<2048, 256>>>(px, pcnt, M);

    const int tiles = (M + 31) / 32;
    for (int blk = 0; blk < 2; ++blk) {
        const int l0 = 2 * blk, l1 = 2 * blk + 1;
        // conv -> BN -> ReLU
        subm_conv_kernel<<<tiles, 256>>>(px, conv_w + (size_t)l0 * 27 * CCH * CCH,
                                         nbr_idx, nbr_mask, py, M);
        zero_stats_kernel<<<1, 256>>>(pstats);
        bn_stats_kernel<<<2048, 128>>>(py, pstats, M);
        bn_apply_kernel<<<2048, 256>>>(py, bn_g + l0 * CCH, bn_b + l0 * CCH, pstats,
                                       (const float*)0, pa, M);
        // conv -> BN -> +residual -> ReLU  (writes back into px)
        subm_conv_kernel<<<tiles, 256>>>(pa, conv_w + (size_t)l1 * 27 * CCH * CCH,
                                         nbr_idx, nbr_mask, py, M);
        zero_stats_kernel<<<1, 256>>>(pstats);
        bn_stats_kernel<<<2048, 128>>>(py, pstats, M);
        bn_apply_kernel<<<2048, 256>>>(py, bn_g + l1 * CCH, bn_b + l1 * CCH, pstats,
                                       px, px, M);
    }

    head_kernel<<<2048, 128>>>(px, gp, inv_idx, w1, b1, w2, b2, out, Np);
}

// round 3
// speedup vs baseline: 3.7667x; 3.7667x over previous
#include <cuda_runtime.h>
#include <cuda_bf16.h>
#include <stdint.h>
#include <math.h>

#define NPTS 200000
#define CCH  128
#define EPSV 1e-5f

// ---------------- scratch (device globals; no allocations anywhere) ----------
__device__ float g_x[NPTS * CCH];               // fp32 pooled feats / residual
__device__ float g_y[NPTS * CCH];               // fp32 conv output
__device__ __nv_bfloat16 g_xb[NPTS * CCH];      // bf16 conv input (x path)
__device__ __nv_bfloat16 g_ab[NPTS * CCH];      // bf16 conv input (mid path)
__device__ __nv_bfloat16 g_wb[4 * 27 * CCH * CCH];  // bf16 conv weights
__device__ float g_cnt[NPTS];
__device__ float g_stats[256];

// ---------------- small helpers ----------------
__device__ __forceinline__ unsigned smem_u32(const void* p) {
    return (unsigned)__cvta_generic_to_shared(p);
}
__device__ __forceinline__ void ldsm_x4(uint32_t* r, unsigned addr) {
    asm volatile("ldmatrix.sync.aligned.m8n8.x4.shared.b16 {%0,%1,%2,%3}, [%4];\n"
                 : "=r"(r[0]), "=r"(r[1]), "=r"(r[2]), "=r"(r[3]) : "r"(addr));
}
__device__ __forceinline__ void ldsm_x4_t(uint32_t* r, unsigned addr) {
    asm volatile("ldmatrix.sync.aligned.m8n8.x4.trans.shared.b16 {%0,%1,%2,%3}, [%4];\n"
                 : "=r"(r[0]), "=r"(r[1]), "=r"(r[2]), "=r"(r[3]) : "r"(addr));
}
__device__ __forceinline__ void mma_bf16(float* c, const uint32_t* a, uint32_t b0, uint32_t b1) {
    asm volatile("mma.sync.aligned.m16n8k16.row.col.f32.bf16.bf16.f32 "
                 "{%0,%1,%2,%3}, {%4,%5,%6,%7}, {%8,%9}, {%0,%1,%2,%3};\n"
                 : "+f"(c[0]), "+f"(c[1]), "+f"(c[2]), "+f"(c[3])
                 : "r"(a[0]), "r"(a[1]), "r"(a[2]), "r"(a[3]), "r"(b0), "r"(b1));
}

// ---------------- zero kernels ----------------
__global__ void zero_pool_kernel(float* x, float* cnt, int M) {
    int total = M * CCH;
    for (int i = blockIdx.x * blockDim.x + threadIdx.x; i < total; i += gridDim.x * blockDim.x)
        x[i] = 0.f;
    for (int i = blockIdx.x * blockDim.x + threadIdx.x; i < M; i += gridDim.x * blockDim.x)
        cnt[i] = 0.f;
}
__global__ void zero_stats_kernel(float* stats) { stats[threadIdx.x] = 0.f; }

// ---------------- weight fp32 -> bf16 conversion ----------------
__global__ void convert_w_kernel(const float* __restrict__ w, __nv_bfloat16* __restrict__ wb, int n) {
    for (int i = blockIdx.x * blockDim.x + threadIdx.x; i < n; i += gridDim.x * blockDim.x)
        wb[i] = __float2bfloat16(w[i]);
}

// ---------------- encoder: Linear(14->128) + LayerNorm + ReLU + segment-sum --
__global__ __launch_bounds__(128)
void encode_pool_kernel(const float* __restrict__ gp,
                        const float* __restrict__ w_enc,
                        const float* __restrict__ b_enc,
                        const float* __restrict__ ln_g,
                        const float* __restrict__ ln_b,
                        const int*   __restrict__ inv_idx,
                        float* __restrict__ xsum,
                        float* __restrict__ cnt,
                        int Np) {
    const int c = threadIdx.x;
    __shared__ float sg[14];
    __shared__ float red[8];

    const float be = b_enc[c];
    const float lg = ln_g[c];
    const float lb = ln_b[c];

    for (int i = blockIdx.x; i < Np; i += gridDim.x) {
        if (c < 14) sg[c] = gp[i * 14 + c];
        __syncthreads();
        float f = be;
#pragma unroll
        for (int k = 0; k < 14; ++k) f += sg[k] * w_enc[k * CCH + c];
        float s = f, s2 = f * f;
#pragma unroll
        for (int off = 16; off > 0; off >>= 1) {
            s  += __shfl_xor_sync(0xffffffffu, s,  off);
            s2 += __shfl_xor_sync(0xffffffffu, s2, off);
        }
        int w = c >> 5;
        if ((c & 31) == 0) { red[w] = s; red[4 + w] = s2; }
        __syncthreads();
        float mu = (red[0] + red[1] + red[2] + red[3]) * (1.f / 128.f);
        float ms = (red[4] + red[5] + red[6] + red[7]) * (1.f / 128.f);
        float inv = rsqrtf(ms - mu * mu + EPSV);
        float v = fmaxf((f - mu) * inv * lg + lb, 0.f);
        int vox = inv_idx[i];
        atomicAdd(&xsum[vox * CCH + c], v);
        if (c == 0) atomicAdd(&cnt[vox], 1.f);
        __syncthreads();
    }
}

// ---------------- pooled sums / counts -> fp32 + bf16 -------------------------
__global__ void pool_div_kernel(float* __restrict__ x, const float* __restrict__ cnt,
                                __nv_bfloat16* __restrict__ xb, int M) {
    int total = M * CCH;
    for (int i = blockIdx.x * blockDim.x + threadIdx.x; i < total; i += gridDim.x * blockDim.x) {
        float v = x[i] / cnt[i >> 7];
        x[i] = v;
        xb[i] = __float2bfloat16(v);
    }
}

// ---------------- submanifold conv via bf16 tensor cores ----------------------
// y[M,128] = sum_o gather_mask(x, o) @ W[o];  128-voxel x 128-ch tile per block.
// 256 threads = 8 warps in 4(row) x 2(col) grid; warp tile 32x64.
__global__ __launch_bounds__(256)
void subm_conv_mma_kernel(const __nv_bfloat16* __restrict__ xin,
                          const __nv_bfloat16* __restrict__ W,   // 27 x 128 x 128 bf16
                          const int*   __restrict__ nbr_idx,
                          const float* __restrict__ nbr_mask,
                          float* __restrict__ y,
                          int M) {
    extern __shared__ __align__(16) char smem_raw[];
    __nv_bfloat16* As = (__nv_bfloat16*)smem_raw;   // 128 x 136
    __nv_bfloat16* Bs = As + 128 * 136;             // 128 x 136
    __shared__ int   sidx[128];
    __shared__ float smsk[128];

    const int tid  = threadIdx.x;
    const int warp = tid >> 5, lane = tid & 31;
    const int wm = warp & 3;        // row group: rows wm*32 .. +31
    const int wn = warp >> 2;       // col group: cols wn*64 .. +63
    const int v0 = blockIdx.x * 128;

    float acc[2][8][4];
#pragma unroll
    for (int mi = 0; mi < 2; ++mi)
#pragma unroll
        for (int ni = 0; ni < 8; ++ni)
#pragma unroll
            for (int q = 0; q < 4; ++q) acc[mi][ni][q] = 0.f;

    for (int o = 0; o < 27; ++o) {
        int pred = 0;
        if (tid < 128) {
            int v = v0 + tid; int id = 0; float mk = 0.f;
            if (v < M) { id = nbr_idx[v * 27 + o]; mk = nbr_mask[v * 27 + o]; }
            sidx[tid] = id; smsk[tid] = mk;
            pred = (mk != 0.f);
        }
        int any = __syncthreads_or(pred);
        if (!any) continue;

        // stage A (gathered; mask is 0/1 -> copy-or-zero) and B (W[o])
        {
            const int row = tid >> 1, half = tid & 1;
            uint4 buf[8];
            if (smsk[row] != 0.f) {
                const uint4* s = (const uint4*)(xin + (size_t)sidx[row] * CCH) + half * 8;
#pragma unroll
                for (int q = 0; q < 8; ++q) buf[q] = s[q];
            } else {
                uint4 z = make_uint4(0, 0, 0, 0);
#pragma unroll
                for (int q = 0; q < 8; ++q) buf[q] = z;
            }
            uint4* dA = (uint4*)(As + row * 136) + half * 8;
#pragma unroll
            for (int q = 0; q < 8; ++q) dA[q] = buf[q];

            const uint4* sB = (const uint4*)(W + (size_t)o * CCH * CCH + row * CCH) + half * 8;
            uint4* dB = (uint4*)(Bs + row * 136) + half * 8;
#pragma unroll
            for (int q = 0; q < 8; ++q) dB[q] = sB[q];
        }
        __syncthreads();

#pragma unroll
        for (int kc = 0; kc < 8; ++kc) {
            uint32_t a[2][4];
#pragma unroll
            for (int mi = 0; mi < 2; ++mi) {
                const __nv_bfloat16* p = As + (wm * 32 + mi * 16 + (lane & 15)) * 136
                                            + kc * 16 + (lane >> 4) * 8;
                ldsm_x4(a[mi], smem_u32(p));
            }
#pragma unroll
            for (int nb = 0; nb < 4; ++nb) {
                uint32_t b[4];
                const __nv_bfloat16* p = Bs + (kc * 16 + (lane & 15)) * 136
                                            + wn * 64 + nb * 16 + (lane >> 4) * 8;
                ldsm_x4_t(b, smem_u32(p));
#pragma unroll
                for (int mi = 0; mi < 2; ++mi) {
                    mma_bf16(acc[mi][nb * 2 + 0], a[mi], b[0], b[1]);
                    mma_bf16(acc[mi][nb * 2 + 1], a[mi], b[2], b[3]);
                }
            }
        }
        __syncthreads();
    }

    // epilogue: write fp32
    const int rbase = v0 + wm * 32 + (lane >> 2);
    const int cbase = wn * 64 + (lane & 3) * 2;
#pragma unroll
    for (int mi = 0; mi < 2; ++mi) {
#pragma unroll
        for (int ni = 0; ni < 8; ++ni) {
            int col = cbase + ni * 8;
            int r0 = rbase + mi * 16;
            if (r0 < M) {
                y[(size_t)r0 * CCH + col]     = acc[mi][ni][0];
                y[(size_t)r0 * CCH + col + 1] = acc[mi][ni][1];
            }
            int r1 = r0 + 8;
            if (r1 < M) {
                y[(size_t)r1 * CCH + col]     = acc[mi][ni][2];
                y[(size_t)r1 * CCH + col + 1] = acc[mi][ni][3];
            }
        }
    }
}

// ---------------- BN stats ----------------
__global__ __launch_bounds__(128)
void bn_stats_kernel(const float* __restrict__ y, float* __restrict__ stats, int M) {
    const int c = threadIdx.x;
    float s1 = 0.f, s2 = 0.f;
    for (int r = blockIdx.x; r < M; r += gridDim.x) {
        float v = y[(size_t)r * CCH + c];
        s1 += v; s2 += v * v;
    }
    atomicAdd(&stats[c], s1);
    atomicAdd(&stats[128 + c], s2);
}

// ---------------- BN apply (+optional residual) + ReLU, dual-dtype out --------
__global__ void bn_apply_kernel(const float* __restrict__ y,
                                const float* __restrict__ g,
                                const float* __restrict__ b,
                                const float* __restrict__ stats,
                                const float* __restrict__ residual,   // nullable
                                float* __restrict__ out_f32,          // nullable
                                __nv_bfloat16* __restrict__ out_b16,  // nullable
                                int M) {
    int total = M * CCH;
    float invM = 1.f / (float)M;
    for (int i = blockIdx.x * blockDim.x + threadIdx.x; i < total; i += gridDim.x * blockDim.x) {
        int c = i & 127;
        float m   = stats[c] * invM;
        float var = stats[128 + c] * invM - m * m;
        float inv = rsqrtf(var + EPSV);
        float v = (y[i] - m) * inv * g[c] + b[c];
        if (residual) v += residual[i];
        v = fmaxf(v, 0.f);
        if (out_f32) out_f32[i] = v;
        if (out_b16) out_b16[i] = __float2bfloat16(v);
    }
}

// ---------------- head: gather + MLP(128->64->14) + residual add --------------
__global__ __launch_bounds__(128)
void head_kernel(const float* __restrict__ x,
                 const float* __restrict__ gp,
                 const int*   __restrict__ inv_idx,
                 const float* __restrict__ w1, const float* __restrict__ b1,
                 const float* __restrict__ w2, const float* __restrict__ b2,
                 float* __restrict__ out, int Np) {
    __shared__ float w1s[CCH * 64];
    __shared__ float w2s[64 * 14];
    __shared__ float b1s[64];
    __shared__ float b2s[14];
    __shared__ float pfs[2][CCH];
    __shared__ float hs[2][64];

    const int tid = threadIdx.x;
    for (int i = tid; i < CCH * 64; i += 128) w1s[i] = w1[i];
    for (int i = tid; i < 64 * 14; i += 128) w2s[i] = w2[i];
    if (tid < 64) b1s[tid] = b1[tid];
    if (tid < 14) b2s[tid] = b2[tid];
    __syncthreads();

    const int h = tid >> 6;
    const int j = tid & 63;

    for (int ip = blockIdx.x * 2; ip < Np; ip += gridDim.x * 2) {
        int i = ip + h;
        bool ok = (i < Np);
        if (ok) {
            int v = inv_idx[i];
            pfs[h][j]      = x[(size_t)v * CCH + j];
            pfs[h][j + 64] = x[(size_t)v * CCH + j + 64];
        }
        __syncthreads();
        if (ok) {
            float acc = b1s[j];
#pragma unroll 8
            for (int k = 0; k < CCH; ++k) acc += pfs[h][k] * w1s[k * 64 + j];
            hs[h][j] = fmaxf(acc, 0.f);
        }
        __syncthreads();
        if (ok && j < 14) {
            float d = b2s[j];
#pragma unroll
            for (int k = 0; k < 64; ++k) d += hs[h][k] * w2s[k * 14 + j];
            out[(size_t)i * 14 + j] = gp[(size_t)i * 14 + j] + d;
        }
        __syncthreads();
    }
}

// ---------------- launch -------------------------------------------------------
extern "C" void kernel_launch(void* const* d_in, const int* in_sizes, int n_in,
                              void* d_out, int out_size) {
    const float* gp       = (const float*)d_in[0];
    const float* w_enc    = (const float*)d_in[1];
    const float* b_enc    = (const float*)d_in[2];
    const float* ln_g     = (const float*)d_in[3];
    const float* ln_b     = (const float*)d_in[4];
    const float* conv_w   = (const float*)d_in[5];
    const float* bn_g     = (const float*)d_in[6];
    const float* bn_b     = (const float*)d_in[7];
    const float* w1       = (const float*)d_in[8];
    const float* b1       = (const float*)d_in[9];
    const float* w2       = (const float*)d_in[10];
    const float* b2       = (const float*)d_in[11];
    const float* nbr_mask = (const float*)d_in[12];
    const int*   inv_idx  = (const int*)d_in[13];
    const int*   nbr_idx  = (const int*)d_in[14];
    float* out = (float*)d_out;

    const int Np = in_sizes[0] / 14;
    const int M  = in_sizes[12] / 27;

    float *px, *py, *pcnt, *pstats;
    __nv_bfloat16 *pxb, *pab, *pwb;
    cudaGetSymbolAddress((void**)&px,     g_x);
    cudaGetSymbolAddress((void**)&py,     g_y);
    cudaGetSymbolAddress((void**)&pxb,    g_xb);
    cudaGetSymbolAddress((void**)&pab,    g_ab);
    cudaGetSymbolAddress((void**)&pwb,    g_wb);
    cudaGetSymbolAddress((void**)&pcnt,   g_cnt);
    cudaGetSymbolAddress((void**)&pstats, g_stats);

    const int CONV_SMEM = 2 * 128 * 136 * 2;   // 69632 bytes
    cudaFuncSetAttribute(subm_conv_mma_kernel,
                         cudaFuncAttributeMaxDynamicSharedMemorySize, CONV_SMEM);

    convert_w_kernel<<<1024, 256>>>(conv_w, pwb, 4 * 27 * CCH * CCH);
    zero_pool_kernel<<<1024, 256>>>(px, pcnt, M);
    encode_pool_kernel<<<4096, 128>>>(gp, w_enc, b_enc, ln_g, ln_b, inv_idx, px, pcnt, Np);
    pool_div_kernel<<<2048, 256>>>(px, pcnt, pxb, M);

    const int tiles = (M + 127) / 128;
    for (int blk = 0; blk < 2; ++blk) {
        const int l0 = 2 * blk, l1 = 2 * blk + 1;
        // conv1 -> BN -> ReLU (bf16 out only)
        subm_conv_mma_kernel<<<tiles, 256, CONV_SMEM>>>(
            pxb, pwb + (size_t)l0 * 27 * CCH * CCH, nbr_idx, nbr_mask, py, M);
        zero_stats_kernel<<<1, 256>>>(pstats);
        bn_stats_kernel<<<2048, 128>>>(py, pstats, M);
        bn_apply_kernel<<<2048, 256>>>(py, bn_g + l0 * CCH, bn_b + l0 * CCH, pstats,
                                       (const float*)0, (float*)0, pab, M);
        // conv2 -> BN -> +residual -> ReLU (fp32 residual + bf16 next input)
        subm_conv_mma_kernel<<<tiles, 256, CONV_SMEM>>>(
            pab, pwb + (size_t)l1 * 27 * CCH * CCH, nbr_idx, nbr_mask, py, M);
        zero_stats_kernel<<<1, 256>>>(pstats);
        bn_stats_kernel<<<2048, 128>>>(py, pstats, M);
        bn_apply_kernel<<<2048, 256>>>(py, bn_g + l1 * CCH, bn_b + l1 * CCH, pstats,
                                       px, px, pxb, M);
    }

    head_kernel<<<2048, 128>>>(px, gp, inv_idx, w1, b1, w2, b2, out, Np);
}